// round 2
// baseline (speedup 1.0000x reference)
#include <cuda_runtime.h>
#include <cuda_fp16.h>
#include <cstdint>

// Problem constants
#define NB   16
#define CINC 512
#define COUTC 256
#define HH   32
#define WW   32
// Combined GEMM: M = 4*256 = 1024, P = NB*H*W = 16384, K = 512 per tap

// -------- device scratch (allocation-free rule: static __device__ globals) ------
__device__ float  g_y[1024 * 16384];          // 64 MB conv output, GEMM layout [m][p]
__device__ __half g_wp[9 * 1024 * 512];       // packed per-tap weights
__device__ __half g_xh[NB * CINC * HH * WW];  // fp16 copy of x
__device__ float  g_bias[1024];
__device__ float  g_psum[1024 * 128];         // per-(m, pixel-block) partial sums
__device__ float  g_qsum[1024 * 128];
__device__ float  g_scale[256];
__device__ float  g_shift[256];

// ---------------- pack weights: Wp[tap][m][c], tap = di*3+dj --------------------
__global__ void pack_weights_kernel(const float* __restrict__ w1, const float* __restrict__ w2,
                                    const float* __restrict__ w3, const float* __restrict__ w4) {
    int idx = blockIdx.x * 256 + threadIdx.x;
    if (idx >= 9 * 1024 * 512) return;
    int t   = idx / (1024 * 512);
    int rem = idx - t * (1024 * 512);
    int m = rem >> 9, c = rem & 511;
    int conv = m >> 8, co = m & 255;
    int di = t / 3, dj = t - di * 3;
    int kh = 3 - (conv & 1), kw = 3 - (conv >> 1);
    float v = 0.f;
    if (di < kh && dj < kw) {
        const float* w = (conv == 0) ? w1 : (conv == 1) ? w2 : (conv == 2) ? w3 : w4;
        v = w[((co * 512 + c) * kh + di) * kw + dj];
    }
    g_wp[((size_t)t * 1024 + m) * 512 + c] = __float2half(v);
}

__global__ void pack_misc_kernel(const float* __restrict__ b1, const float* __restrict__ b2,
                                 const float* __restrict__ b3, const float* __restrict__ b4) {
    int m = blockIdx.x * 256 + threadIdx.x;  // 1024
    int conv = m >> 8, co = m & 255;
    const float* b = (conv == 0) ? b1 : (conv == 1) ? b2 : (conv == 2) ? b3 : b4;
    g_bias[m] = b[co];
}

__global__ void convert_x_kernel(const float* __restrict__ x) {
    int i = blockIdx.x * 256 + threadIdx.x;  // 8388608 / 4 threads, float4 loads
    const float4* x4 = (const float4*)x;
    float4 v = x4[i];
    __half2* o2 = (__half2*)g_xh;
    o2[i * 2    ] = __floats2half2_rn(v.x, v.y);
    o2[i * 2 + 1] = __floats2half2_rn(v.z, v.w);
}

// ------------------------------- conv (implicit GEMM) ---------------------------
// Block: 256 threads = 8 warps. Tile: BM=128 channels x BN=128 pixels (one image n,
// rows i0..i0+3, full 32 cols). Warp tile: 64(m) x 32(n) -> each warp owns one
// output row r. K loop: chunks of 32 channels; x patch (with halo) loaded once per
// chunk into smem and reused by all taps of this conv.
__global__ void __launch_bounds__(256, 2) conv_kernel() {
    __shared__ __align__(16) __half Xs[32][6][36];   // [c][patch row][patch col]
    __shared__ __align__(16) __half Ws[128][40];     // [m][c], padded stride 80B
    __shared__ float s_ps[4][128];
    __shared__ float s_qs[4][128];

    const int tid  = threadIdx.x;
    const int lane = tid & 31, warp = tid >> 5;
    const int mw = warp & 1;        // 0..1 : 64-row half
    const int r  = warp >> 1;       // 0..3 : output row within the 4-row group
    const int m0 = blockIdx.y << 7;
    const int conv = blockIdx.y >> 1;
    const int KH = 3 - (conv & 1), KW = 3 - (conv >> 1);
    const int pb = blockIdx.x;      // 0..127
    const int n  = pb >> 3;
    const int i0 = (pb & 7) << 2;

    float acc[4][4][4];
    #pragma unroll
    for (int i = 0; i < 4; i++)
        #pragma unroll
        for (int j = 0; j < 4; j++)
            #pragma unroll
            for (int k = 0; k < 4; k++) acc[i][j][k] = 0.f;

    const __half* xbase = g_xh + (size_t)n * (512 * 1024);

    for (int c0 = 0; c0 < 512; c0 += 32) {
        __syncthreads();  // all reads of prior chunk's Xs/Ws complete
        // ---- load x patch (32 ch x 6 rows x 36 cols, zero halo) ----
        #pragma unroll
        for (int it = 0; it < 27; it++) {           // 27*256 = 6912 elements exactly
            int idx = it * 256 + tid;
            int cc  = idx / 216;
            int rem = idx - cc * 216;
            int rr  = rem / 36;
            int col = rem - rr * 36;
            int xi = i0 - 1 + rr, xj = col - 1;
            __half v = __float2half(0.f);
            if ((unsigned)xi < 32u && (unsigned)xj < 32u)
                v = xbase[((c0 + cc) << 10) + (xi << 5) + xj];
            Xs[cc][rr][col] = v;
        }
        for (int di = 0; di < KH; di++)
        for (int dj = 0; dj < KW; dj++) {
            __syncthreads();  // Xs ready / prior tap's Ws reads done
            const __half* wsrc = g_wp + (((size_t)(di * 3 + dj) * 1024 + m0) << 9) + c0;
            #pragma unroll
            for (int it = 0; it < 16; it++) {       // 16*256 = 4096 = 128x32
                int idx = it * 256 + tid;
                int mm = idx >> 5, cc = idx & 31;
                Ws[mm][cc] = wsrc[mm * 512 + cc];
            }
            __syncthreads();
            #pragma unroll
            for (int ks = 0; ks < 32; ks += 16) {
                uint32_t a[4][4];
                #pragma unroll
                for (int mt = 0; mt < 4; mt++) {
                    uint32_t addr = (uint32_t)__cvta_generic_to_shared(
                        &Ws[mw * 64 + mt * 16 + (lane & 15)][ks + ((lane >> 4) << 3)]);
                    asm volatile(
                        "ldmatrix.sync.aligned.m8n8.x4.shared.b16 {%0,%1,%2,%3}, [%4];"
                        : "=r"(a[mt][0]), "=r"(a[mt][1]), "=r"(a[mt][2]), "=r"(a[mt][3])
                        : "r"(addr));
                }
                const int prow = r + di;
                const int cb   = ks + ((lane & 3) << 1);
                #pragma unroll
                for (int nt = 0; nt < 4; nt++) {
                    const int pcol = nt * 8 + (lane >> 2) + dj;
                    __half2 lo = __halves2half2(Xs[cb    ][prow][pcol], Xs[cb + 1][prow][pcol]);
                    __half2 hi = __halves2half2(Xs[cb + 8][prow][pcol], Xs[cb + 9][prow][pcol]);
                    uint32_t b0 = *reinterpret_cast<uint32_t*>(&lo);
                    uint32_t b1 = *reinterpret_cast<uint32_t*>(&hi);
                    #pragma unroll
                    for (int mt = 0; mt < 4; mt++) {
                        asm volatile(
                            "mma.sync.aligned.m16n8k16.row.col.f32.f16.f16.f32 "
                            "{%0,%1,%2,%3}, {%4,%5,%6,%7}, {%8,%9}, {%0,%1,%2,%3};"
                            : "+f"(acc[mt][nt][0]), "+f"(acc[mt][nt][1]),
                              "+f"(acc[mt][nt][2]), "+f"(acc[mt][nt][3])
                            : "r"(a[mt][0]), "r"(a[mt][1]), "r"(a[mt][2]), "r"(a[mt][3]),
                              "r"(b0), "r"(b1));
                    }
                }
            }
        }
    }

    // ---- epilogue: bias, store y, deterministic per-block BN partial sums ----
    const int pbase = (n << 10) + ((i0 + r) << 5);
    #pragma unroll
    for (int mt = 0; mt < 4; mt++) {
        #pragma unroll
        for (int h = 0; h < 2; h++) {
            int mloc = mw * 64 + mt * 16 + h * 8 + (lane >> 2);
            int m = m0 + mloc;
            float bias = g_bias[m];
            float s = 0.f, q = 0.f;
            float* yrow = g_y + (size_t)m * 16384 + pbase + ((lane & 3) << 1);
            #pragma unroll
            for (int nt = 0; nt < 4; nt++) {
                float v0 = acc[mt][nt][h * 2]     + bias;
                float v1 = acc[mt][nt][h * 2 + 1] + bias;
                *reinterpret_cast<float2*>(yrow + nt * 8) = make_float2(v0, v1);
                s += v0 + v1;
                q += v0 * v0 + v1 * v1;
            }
            s += __shfl_xor_sync(0xffffffffu, s, 1);
            s += __shfl_xor_sync(0xffffffffu, s, 2);
            q += __shfl_xor_sync(0xffffffffu, q, 1);
            q += __shfl_xor_sync(0xffffffffu, q, 2);
            if ((lane & 3) == 0) { s_ps[r][mloc] = s; s_qs[r][mloc] = q; }
        }
    }
    __syncthreads();
    if (tid < 128) {
        float s = s_ps[0][tid] + s_ps[1][tid] + s_ps[2][tid] + s_ps[3][tid];
        float q = s_qs[0][tid] + s_qs[1][tid] + s_qs[2][tid] + s_qs[3][tid];
        g_psum[(size_t)(m0 + tid) * 128 + pb] = s;
        g_qsum[(size_t)(m0 + tid) * 128 + pb] = q;
    }
}

// ---------------- BN stats: mean/var per cout over all 4 convs ------------------
// One block per output channel: 128 threads, each channel sums 4 convs x 128 blocks.
__global__ void stats_kernel(const float* __restrict__ gamma, const float* __restrict__ beta) {
    __shared__ float sh_s[128], sh_q[128];
    int co = blockIdx.x;        // 256 blocks
    int t  = threadIdx.x;       // 128 threads
    float s = 0.f, q = 0.f;
    #pragma unroll
    for (int conv = 0; conv < 4; conv++) {
        size_t base = (size_t)(conv * 256 + co) * 128 + t;
        s += g_psum[base];
        q += g_qsum[base];
    }
    sh_s[t] = s; sh_q[t] = q;
    __syncthreads();
    for (int off = 64; off >= 32; off >>= 1) {
        if (t < off) { sh_s[t] += sh_s[t + off]; sh_q[t] += sh_q[t + off]; }
        __syncthreads();
    }
    if (t < 32) {
        s = sh_s[t]; q = sh_q[t];
        #pragma unroll
        for (int off = 16; off >= 1; off >>= 1) {
            s += __shfl_xor_sync(0xffffffffu, s, off);
            q += __shfl_xor_sync(0xffffffffu, q, off);
        }
        if (t == 0) {
            float mean = s * (1.f / 65536.f);
            float var  = q * (1.f / 65536.f) - mean * mean;
            float sc   = gamma[co] * rsqrtf(var + 1e-5f);
            g_scale[co] = sc;
            g_shift[co] = beta[co] - mean * sc;
        }
    }
}

// ------------- BN apply + ReLU + pixel-shuffle interleave to d_out --------------
// Each thread makes one float4 of output: 4 consecutive J values -> conv pairs
// alternate only in J parity, so 2 source rows of g_y, consecutive p.
__global__ void bn_kernel(float* __restrict__ out) {
    int o4 = blockIdx.x * 256 + threadIdx.x;   // 4194304 = 16777216/4
    int o  = o4 << 2;
    int J  = o & 63;           // J, J+1, J+2, J+3 (J multiple of 4)
    int I  = (o >> 6) & 63;
    int co = (o >> 12) & 255;
    int n  = o >> 20;
    int convA = (I & 1);            // J even
    int convB = (I & 1) | 2;        // J odd
    int p = (n << 10) + ((I >> 1) << 5) + (J >> 1);   // J/2, then +1 for J+2
    const float* ya = g_y + (size_t)((convA << 8) | co) * 16384 + p;
    const float* yb = g_y + (size_t)((convB << 8) | co) * 16384 + p;
    float sa = g_scale[co], sha = g_shift[co];
    float4 r;
    r.x = fmaxf(ya[0] * sa + sha, 0.f);
    r.y = fmaxf(yb[0] * sa + sha, 0.f);
    r.z = fmaxf(ya[1] * sa + sha, 0.f);
    r.w = fmaxf(yb[1] * sa + sha, 0.f);
    reinterpret_cast<float4*>(out)[o4] = r;
}

// --------------------------------- launch ---------------------------------------
extern "C" void kernel_launch(void* const* d_in, const int* in_sizes, int n_in,
                              void* d_out, int out_size) {
    const float* x     = (const float*)d_in[0];
    const float* w1    = (const float*)d_in[1];
    const float* b1    = (const float*)d_in[2];
    const float* w2    = (const float*)d_in[3];
    const float* b2    = (const float*)d_in[4];
    const float* w3    = (const float*)d_in[5];
    const float* b3    = (const float*)d_in[6];
    const float* w4    = (const float*)d_in[7];
    const float* b4    = (const float*)d_in[8];
    const float* gamma = (const float*)d_in[9];
    const float* beta  = (const float*)d_in[10];
    float* out = (float*)d_out;

    pack_weights_kernel<<<(9 * 1024 * 512 + 255) / 256, 256>>>(w1, w2, w3, w4);
    pack_misc_kernel<<<4, 256>>>(b1, b2, b3, b4);
    convert_x_kernel<<<(8388608 / 4) / 256, 256>>>(x);
    dim3 grid(128, 8);
    conv_kernel<<<grid, 256>>>();
    stats_kernel<<<256, 128>>>(gamma, beta);
    bn_kernel<<<(16777216 / 4) / 256, 256>>>(out);
}

// round 4
// speedup vs baseline: 2.3265x; 2.3265x over previous
#include <cuda_runtime.h>
#include <cuda_fp16.h>
#include <cstdint>

// Problem: 4 convs (3x3, 2x3, 3x2, 2x2) on x[16,512,32,32] -> interleave -> BN -> ReLU
// GEMM view: M = pixels (16384), N = 4*256 couts (1024), K = 512 per tap.
// M=pixels / N=couts operand roles so BOTH mma operands come from ldmatrix
// (A from NHWC x-patch, B=weights [cout][k] = col-major B, NON-trans ldmatrix);
// taps are pure address shifts into the staged patch; cp.async 3-stage pipeline.

#define NB   16

// -------- device scratch (allocation-free rule: static __device__ globals) ------
__device__ float  g_y[1024 * 16384];          // conv output [m][p]
__device__ __half g_wp[9 * 1024 * 512];       // packed per-tap weights [tap][m][c]
__device__ __half g_xh[NB * 32 * 32 * 512];   // x in NHWC fp16: [n][i][j][c]
__device__ float  g_bias[1024];
__device__ float  g_psum[1024 * 128];
__device__ float  g_qsum[1024 * 128];
__device__ float  g_scale[256];
__device__ float  g_shift[256];

// ---------------- pack weights: Wp[tap][m][c], tap = di*3+dj --------------------
__global__ void pack_weights_kernel(const float* __restrict__ w1, const float* __restrict__ w2,
                                    const float* __restrict__ w3, const float* __restrict__ w4) {
    int idx = blockIdx.x * 256 + threadIdx.x;
    if (idx >= 9 * 1024 * 512) return;
    int t   = idx / (1024 * 512);
    int rem = idx - t * (1024 * 512);
    int m = rem >> 9, c = rem & 511;
    int conv = m >> 8, co = m & 255;
    int di = t / 3, dj = t - di * 3;
    int kh = 3 - (conv & 1), kw = 3 - (conv >> 1);
    float v = 0.f;
    if (di < kh && dj < kw) {
        const float* w = (conv == 0) ? w1 : (conv == 1) ? w2 : (conv == 2) ? w3 : w4;
        v = w[((co * 512 + c) * kh + di) * kw + dj];
    }
    g_wp[((size_t)t * 1024 + m) * 512 + c] = __float2half(v);
}

__global__ void pack_misc_kernel(const float* __restrict__ b1, const float* __restrict__ b2,
                                 const float* __restrict__ b3, const float* __restrict__ b4) {
    int m = blockIdx.x * 256 + threadIdx.x;
    int conv = m >> 8, co = m & 255;
    const float* b = (conv == 0) ? b1 : (conv == 1) ? b2 : (conv == 2) ? b3 : b4;
    g_bias[m] = b[co];
}

// ---- NCHW fp32 -> NHWC fp16 transpose (smem-tiled, coalesced both sides) -------
__global__ void convert_x_kernel(const float* __restrict__ x) {
    __shared__ float tile[32][33];
    int ni = blockIdx.x;            // n*32 + i  (512)
    int c0 = blockIdx.y << 5;       // 16 tiles of 32 channels
    int n = ni >> 5, i = ni & 31;
    int tid = threadIdx.x;
    #pragma unroll
    for (int it = 0; it < 4; it++) {
        int cc = it * 8 + (tid >> 5);
        int j  = tid & 31;
        tile[cc][j] = x[(((size_t)n * 512 + c0 + cc) << 10) + (i << 5) + j];
    }
    __syncthreads();
    int j   = tid >> 3;
    int cc0 = (tid & 7) << 2;
    __half2 lo = __floats2half2_rn(tile[cc0][j], tile[cc0 + 1][j]);
    __half2 hi = __floats2half2_rn(tile[cc0 + 2][j], tile[cc0 + 3][j]);
    uint2 v = make_uint2(*(uint32_t*)&lo, *(uint32_t*)&hi);
    *reinterpret_cast<uint2*>(g_xh + ((((size_t)ni << 5) + j) << 9) + c0 + cc0) = v;
}

// ------------------------------- conv (implicit GEMM) ---------------------------
// 256 thr = 8 warps. CTA tile: 128 pixels (one n, rows i0..i0+3, 32 cols) x 128 couts.
// Warp tile: 32 pixels (one row) x 64 couts. K-chunks of 32 channels.
// smem (dynamic): Xs[2][6][36][40] halves, Ws[3][128][40] halves.
#define XS_STRIDE 40
#define XS_BUF    (6 * 36 * XS_STRIDE)       // halves per Xs buffer
#define WS_BUF    (128 * XS_STRIDE)          // halves per Ws buffer
#define SMEM_HALVES (2 * XS_BUF + 3 * WS_BUF)
#define SMEM_BYTES  (SMEM_HALVES * 2)

#define CP16(dst, src, sz) \
    asm volatile("cp.async.cg.shared.global [%0], [%1], 16, %2;" \
                 :: "r"(dst), "l"(src), "r"(sz))

__global__ void __launch_bounds__(256, 2) conv_kernel() {
    extern __shared__ __align__(128) __half smem[];
    __half* Xs = smem;                    // 2 buffers
    __half* Ws = smem + 2 * XS_BUF;       // 3 buffers
    float* s_ps = reinterpret_cast<float*>(smem);        // reused after mainloop
    float* s_qs = reinterpret_cast<float*>(smem) + 512;  // [4][128] each

    const int tid  = threadIdx.x;
    const int lane = tid & 31, warp = tid >> 5;
    const int r     = warp >> 1;          // 0..3 pixel row
    const int nwarp = warp & 1;           // 0..1 cout half
    const int nbase = nwarp << 6;
    const int m0   = blockIdx.y << 7;
    const int conv = blockIdx.y >> 1;
    const int KH = 3 - (conv & 1), KW = 3 - (conv >> 1);
    const int ntaps = KH * KW;
    const int S = 16 * ntaps;
    const int pb = blockIdx.x;
    const int n  = pb >> 3;
    const int i0 = (pb & 7) << 2;

    const uint32_t xs_s = (uint32_t)__cvta_generic_to_shared(Xs);
    const uint32_t ws_s = (uint32_t)__cvta_generic_to_shared(Ws);

    // lane-invariant ldmatrix offsets
    const int la15 = lane & 15;                 // A: pixel-in-tile
    const int lahi = (lane >> 4) << 3;          // A: k sub-offset
    const int bm   = (lane & 7) + ((lane >> 4) << 3);  // B: cout-in-16
    const int bk   = ((lane >> 3) & 1) << 3;           // B: k sub-offset

    float acc[2][8][4];
    #pragma unroll
    for (int a = 0; a < 2; a++)
        #pragma unroll
        for (int b = 0; b < 8; b++)
            #pragma unroll
            for (int c = 0; c < 4; c++) acc[a][b][c] = 0.f;

    // ---- stage load: stage s -> chunk = s/ntaps, tap = s%ntaps ----
    auto issue = [&](int s) {
        int c_idx = s / ntaps;
        int tt    = s - c_idx * ntaps;
        int c0    = c_idx << 5;
        if (tt == 0) {
            // Xs chunk load: 216 pixels x 4 x 16B, zero-fill halo via src-size 0
            uint32_t xdst = xs_s + ((c_idx & 1) * XS_BUF) * 2;
            #pragma unroll
            for (int it = 0; it < 4; it++) {
                int idx = it * 256 + tid;
                if (idx < 864) {
                    int pixel = idx >> 2, seg = idx & 3;
                    int rr = pixel / 36, col = pixel - rr * 36;
                    int xi = i0 - 1 + rr, xj = col - 1;
                    bool inb = ((unsigned)xi < 32u) & ((unsigned)xj < 32u);
                    const __half* src = inb
                        ? g_xh + ((((size_t)(n * 32 + xi)) << 5) + xj) * 512 + c0 + (seg << 3)
                        : g_xh;
                    CP16(xdst + (pixel * XS_STRIDE + (seg << 3)) * 2, src, inb ? 16 : 0);
                }
            }
        }
        // Ws tap load: 128 rows x 4 x 16B
        int di = tt / KW, dj = tt - di * KW;
        int tap = di * 3 + dj;
        uint32_t wdst = ws_s + ((s % 3) * WS_BUF) * 2;
        const __half* wsrc = g_wp + (((size_t)tap * 1024 + m0) << 9) + c0;
        #pragma unroll
        for (int it = 0; it < 2; it++) {
            int idx = it * 256 + tid;
            int mm = idx >> 2, seg = idx & 3;
            CP16(wdst + (mm * XS_STRIDE + (seg << 3)) * 2, wsrc + mm * 512 + (seg << 3), 16);
        }
    };

    issue(0); asm volatile("cp.async.commit_group;");
    issue(1); asm volatile("cp.async.commit_group;");

    for (int s = 0; s < S; s++) {
        asm volatile("cp.async.wait_group 1;");
        __syncthreads();
        if (s + 2 < S) issue(s + 2);
        asm volatile("cp.async.commit_group;");

        int c_idx = s / ntaps;
        int tt    = s - c_idx * ntaps;
        int di = tt / KW, dj = tt - di * KW;
        const uint32_t xb = xs_s + ((c_idx & 1) * XS_BUF) * 2;
        const uint32_t wb = ws_s + ((s % 3) * WS_BUF) * 2;
        const int prow = r + di;

        #pragma unroll
        for (int ks = 0; ks < 32; ks += 16) {
            uint32_t a[2][4], b[4][4];
            #pragma unroll
            for (int mt = 0; mt < 2; mt++) {
                uint32_t addr = xb + (((prow * 36 + mt * 16 + la15 + dj) * XS_STRIDE) + ks + lahi) * 2;
                asm volatile("ldmatrix.sync.aligned.m8n8.x4.shared.b16 {%0,%1,%2,%3}, [%4];"
                             : "=r"(a[mt][0]), "=r"(a[mt][1]), "=r"(a[mt][2]), "=r"(a[mt][3])
                             : "r"(addr));
            }
            #pragma unroll
            for (int g = 0; g < 4; g++) {
                uint32_t addr = wb + (((nbase + g * 16 + bm) * XS_STRIDE) + ks + bk) * 2;
                asm volatile("ldmatrix.sync.aligned.m8n8.x4.shared.b16 {%0,%1,%2,%3}, [%4];"
                             : "=r"(b[g][0]), "=r"(b[g][1]), "=r"(b[g][2]), "=r"(b[g][3])
                             : "r"(addr));
            }
            #pragma unroll
            for (int mt = 0; mt < 2; mt++)
                #pragma unroll
                for (int nt = 0; nt < 8; nt++) {
                    asm volatile(
                        "mma.sync.aligned.m16n8k16.row.col.f32.f16.f16.f32 "
                        "{%0,%1,%2,%3}, {%4,%5,%6,%7}, {%8,%9}, {%0,%1,%2,%3};"
                        : "+f"(acc[mt][nt][0]), "+f"(acc[mt][nt][1]),
                          "+f"(acc[mt][nt][2]), "+f"(acc[mt][nt][3])
                        : "r"(a[mt][0]), "r"(a[mt][1]), "r"(a[mt][2]), "r"(a[mt][3]),
                          "r"(b[nt >> 1][(nt & 1) * 2]), "r"(b[nt >> 1][(nt & 1) * 2 + 1]));
                }
        }
    }

    __syncthreads();   // done with smem buffers; reuse for BN partials

    // ---- epilogue: bias, store y[m][p], deterministic BN partial sums ----
    // acc[mt][nt][c]: pixel = pbase + mt*16 + (lane>>2) + (c>=2?8:0),
    //                 cout  = nbase + nt*8 + (lane&3)*2 + (c&1)
    const int pbase = (n << 10) + ((i0 + r) << 5);
    const int pc = pbase + (lane >> 2);
    #pragma unroll
    for (int nt = 0; nt < 8; nt++) {
        int cl = nbase + nt * 8 + ((lane & 3) << 1);  // local cout (even)
        int mg = m0 + cl;
        float b0 = g_bias[mg], b1 = g_bias[mg + 1];
        float s0 = 0.f, q0 = 0.f, s1 = 0.f, q1 = 0.f;
        float* y0 = g_y + (size_t)mg * 16384;
        float* y1 = y0 + 16384;
        #pragma unroll
        for (int mt = 0; mt < 2; mt++) {
            int p = pc + mt * 16;
            float v00 = acc[mt][nt][0] + b0;
            float v01 = acc[mt][nt][1] + b1;
            float v10 = acc[mt][nt][2] + b0;
            float v11 = acc[mt][nt][3] + b1;
            y0[p]     = v00;  y1[p]     = v01;
            y0[p + 8] = v10;  y1[p + 8] = v11;
            s0 += v00 + v10;  q0 += v00 * v00 + v10 * v10;
            s1 += v01 + v11;  q1 += v01 * v01 + v11 * v11;
        }
        #pragma unroll
        for (int off = 4; off <= 16; off <<= 1) {
            s0 += __shfl_xor_sync(0xffffffffu, s0, off);
            q0 += __shfl_xor_sync(0xffffffffu, q0, off);
            s1 += __shfl_xor_sync(0xffffffffu, s1, off);
            q1 += __shfl_xor_sync(0xffffffffu, q1, off);
        }
        if (lane < 4) {
            s_ps[r * 128 + cl]     = s0;  s_qs[r * 128 + cl]     = q0;
            s_ps[r * 128 + cl + 1] = s1;  s_qs[r * 128 + cl + 1] = q1;
        }
    }
    __syncthreads();
    if (tid < 128) {
        float s = s_ps[tid] + s_ps[128 + tid] + s_ps[256 + tid] + s_ps[384 + tid];
        float q = s_qs[tid] + s_qs[128 + tid] + s_qs[256 + tid] + s_qs[384 + tid];
        g_psum[(size_t)(m0 + tid) * 128 + pb] = s;
        g_qsum[(size_t)(m0 + tid) * 128 + pb] = q;
    }
}

// ---------------- BN stats ------------------------------------------------------
__global__ void stats_kernel(const float* __restrict__ gamma, const float* __restrict__ beta) {
    __shared__ float sh_s[128], sh_q[128];
    int co = blockIdx.x;
    int t  = threadIdx.x;
    float s = 0.f, q = 0.f;
    #pragma unroll
    for (int conv = 0; conv < 4; conv++) {
        size_t base = (size_t)(conv * 256 + co) * 128 + t;
        s += g_psum[base];
        q += g_qsum[base];
    }
    sh_s[t] = s; sh_q[t] = q;
    __syncthreads();
    for (int off = 64; off >= 32; off >>= 1) {
        if (t < off) { sh_s[t] += sh_s[t + off]; sh_q[t] += sh_q[t + off]; }
        __syncthreads();
    }
    if (t < 32) {
        s = sh_s[t]; q = sh_q[t];
        #pragma unroll
        for (int off = 16; off >= 1; off >>= 1) {
            s += __shfl_xor_sync(0xffffffffu, s, off);
            q += __shfl_xor_sync(0xffffffffu, q, off);
        }
        if (t == 0) {
            float mean = s * (1.f / 65536.f);
            float var  = q * (1.f / 65536.f) - mean * mean;
            float sc   = gamma[co] * rsqrtf(var + 1e-5f);
            g_scale[co] = sc;
            g_shift[co] = beta[co] - mean * sc;
        }
    }
}

// ------------- BN apply + ReLU + pixel-shuffle interleave -----------------------
__global__ void bn_kernel(float* __restrict__ out) {
    int o4 = blockIdx.x * 256 + threadIdx.x;
    int o  = o4 << 2;
    int J  = o & 63;
    int I  = (o >> 6) & 63;
    int co = (o >> 12) & 255;
    int n  = o >> 20;
    int convA = (I & 1);
    int convB = (I & 1) | 2;
    int p = (n << 10) + ((I >> 1) << 5) + (J >> 1);
    const float* ya = g_y + (size_t)((convA << 8) | co) * 16384 + p;
    const float* yb = g_y + (size_t)((convB << 8) | co) * 16384 + p;
    float sa = g_scale[co], sha = g_shift[co];
    float4 r;
    r.x = fmaxf(ya[0] * sa + sha, 0.f);
    r.y = fmaxf(yb[0] * sa + sha, 0.f);
    r.z = fmaxf(ya[1] * sa + sha, 0.f);
    r.w = fmaxf(yb[1] * sa + sha, 0.f);
    reinterpret_cast<float4*>(out)[o4] = r;
}

// --------------------------------- launch ---------------------------------------
extern "C" void kernel_launch(void* const* d_in, const int* in_sizes, int n_in,
                              void* d_out, int out_size) {
    const float* x     = (const float*)d_in[0];
    const float* w1    = (const float*)d_in[1];
    const float* b1    = (const float*)d_in[2];
    const float* w2    = (const float*)d_in[3];
    const float* b2    = (const float*)d_in[4];
    const float* w3    = (const float*)d_in[5];
    const float* b3    = (const float*)d_in[6];
    const float* w4    = (const float*)d_in[7];
    const float* b4    = (const float*)d_in[8];
    const float* gamma = (const float*)d_in[9];
    const float* beta  = (const float*)d_in[10];
    float* out = (float*)d_out;

    static bool attr_set = false;
    if (!attr_set) {
        cudaFuncSetAttribute(conv_kernel, cudaFuncAttributeMaxDynamicSharedMemorySize, SMEM_BYTES);
        attr_set = true;
    }

    pack_weights_kernel<<<(9 * 1024 * 512 + 255) / 256, 256>>>(w1, w2, w3, w4);
    pack_misc_kernel<<<4, 256>>>(b1, b2, b3, b4);
    {
        dim3 g(512, 16);
        convert_x_kernel<<<g, 256>>>(x);
    }
    {
        dim3 grid(128, 8);
        conv_kernel<<<grid, 256, SMEM_BYTES>>>();
    }
    stats_kernel<<<256, 128>>>(gamma, beta);
    bn_kernel<<<(16777216 / 4) / 256, 256>>>(out);
}

// round 6
// speedup vs baseline: 2.7806x; 1.1952x over previous
#include <cuda_runtime.h>
#include <cuda_fp16.h>
#include <cstdint>

// 4 convs (3x3,2x3,3x2,2x2) on x[16,512,32,32] -> interleave -> BN -> ReLU.
// mma.sync implicit GEMM (tcgen05 unavailable: harness PTX target is plain sm_103).
// CTA 128 pixels x 128 couts; stage = (32-ch chunk, kernel row di) covering all KW
// taps -> 48/32/32/16 barriers instead of 144/96/96/64. Ws 2-slot ring, Xs 2-slot.

#define NB 16

__device__ __half g_y[1024 * 16384];          // conv output [m][p], fp16
__device__ __half g_wp[9 * 1024 * 512];       // packed per-tap weights [tap][m][c]
__device__ __half g_xh[NB * 32 * 32 * 512];   // x NHWC fp16 [n][i][j][c]
__device__ float  g_bias[1024];
__device__ float  g_psum[1024 * 128];
__device__ float  g_qsum[1024 * 128];
__device__ float  g_scale[256];
__device__ float  g_shift[256];

// ---------------- pack weights: Wp[tap][m][c], tap = di*3+dj --------------------
__global__ void pack_weights_kernel(const float* __restrict__ w1, const float* __restrict__ w2,
                                    const float* __restrict__ w3, const float* __restrict__ w4) {
    int idx = blockIdx.x * 256 + threadIdx.x;
    if (idx >= 9 * 1024 * 512) return;
    int t   = idx / (1024 * 512);
    int rem = idx - t * (1024 * 512);
    int m = rem >> 9, c = rem & 511;
    int conv = m >> 8, co = m & 255;
    int di = t / 3, dj = t - di * 3;
    int kh = 3 - (conv & 1), kw = 3 - (conv >> 1);
    float v = 0.f;
    if (di < kh && dj < kw) {
        const float* w = (conv == 0) ? w1 : (conv == 1) ? w2 : (conv == 2) ? w3 : w4;
        v = w[((co * 512 + c) * kh + di) * kw + dj];
    }
    g_wp[((size_t)t * 1024 + m) * 512 + c] = __float2half(v);
}

__global__ void pack_misc_kernel(const float* __restrict__ b1, const float* __restrict__ b2,
                                 const float* __restrict__ b3, const float* __restrict__ b4) {
    int m = blockIdx.x * 256 + threadIdx.x;
    int conv = m >> 8, co = m & 255;
    const float* b = (conv == 0) ? b1 : (conv == 1) ? b2 : (conv == 2) ? b3 : b4;
    g_bias[m] = b[co];
}

// ---- NCHW fp32 -> NHWC fp16 (smem-tiled transpose) -----------------------------
__global__ void convert_x_kernel(const float* __restrict__ x) {
    __shared__ float tile[32][33];
    int ni = blockIdx.x;
    int c0 = blockIdx.y << 5;
    int n = ni >> 5, i = ni & 31;
    int tid = threadIdx.x;
    #pragma unroll
    for (int it = 0; it < 4; it++) {
        int cc = it * 8 + (tid >> 5);
        int j  = tid & 31;
        tile[cc][j] = x[(((size_t)n * 512 + c0 + cc) << 10) + (i << 5) + j];
    }
    __syncthreads();
    int j   = tid >> 3;
    int cc0 = (tid & 7) << 2;
    __half2 lo = __floats2half2_rn(tile[cc0][j], tile[cc0 + 1][j]);
    __half2 hi = __floats2half2_rn(tile[cc0 + 2][j], tile[cc0 + 3][j]);
    uint2 v = make_uint2(*(uint32_t*)&lo, *(uint32_t*)&hi);
    *reinterpret_cast<uint2*>(g_xh + ((((size_t)ni << 5) + j) << 9) + c0 + cc0) = v;
}

// ------------------------------- conv (implicit GEMM) ---------------------------
// smem: Xs 2 x [216 pixels][40] halves (17280B each), Ws 2 x [KW(<=3)][128][40]
// (30720B each). Total 96000B. Epilogue reuses blob as Dt[128][132] floats.
#define XS_STRIDE 40
#define XS_BUFB   17280
#define WS_OFF    (2 * XS_BUFB)
#define WS_SLOTB  30720
#define WS_TAPB   10240
#define SMEM_BYTES (2 * XS_BUFB + 2 * WS_SLOTB)

#define CP16(dst, src, sz) \
    asm volatile("cp.async.cg.shared.global [%0], [%1], 16, %2;" \
                 :: "r"(dst), "l"(src), "r"(sz))

__global__ void __launch_bounds__(256, 2) conv_kernel() {
    extern __shared__ __align__(128) unsigned char dsmem[];
    const uint32_t blob = (uint32_t)__cvta_generic_to_shared(dsmem);

    const int tid  = threadIdx.x;
    const int lane = tid & 31, warp = tid >> 5;
    const int r     = warp >> 1;           // pixel row 0..3
    const int nbase = (warp & 1) << 6;     // cout half
    const int m0   = blockIdx.y << 7;
    const int conv = blockIdx.y >> 1;
    const int KH = 3 - (conv & 1), KW = 3 - (conv >> 1);
    const int T  = 16 * KH;                // stages
    const int pb = blockIdx.x;
    const int n  = pb >> 3;
    const int i0 = (pb & 7) << 2;

    const int la15 = lane & 15;
    const int lahi = (lane >> 4) << 3;
    const int bm   = (lane & 7) + ((lane >> 4) << 3);
    const int bk   = ((lane >> 3) & 1) << 3;

    float acc[2][8][4];
    #pragma unroll
    for (int a = 0; a < 2; a++)
        #pragma unroll
        for (int b = 0; b < 8; b++)
            #pragma unroll
            for (int c = 0; c < 4; c++) acc[a][b][c] = 0.f;

    auto issueXs = [&](int chunk) {        // 216 pixels x 4 segs, zero halo
        int c0 = chunk << 5;
        uint32_t xdst = blob + (chunk & 1) * XS_BUFB;
        #pragma unroll
        for (int it = 0; it < 4; it++) {
            int idx = it * 256 + tid;
            if (idx < 864) {
                int pixel = idx >> 2, seg = idx & 3;
                int rr = pixel / 36, col = pixel - rr * 36;
                int xi = i0 - 1 + rr, xj = col - 1;
                bool inb = ((unsigned)xi < 32u) & ((unsigned)xj < 32u);
                const __half* src = inb
                    ? g_xh + ((((size_t)(n * 32 + xi)) << 5) + xj) * 512 + c0 + (seg << 3)
                    : g_xh;
                CP16(xdst + (pixel * XS_STRIDE + (seg << 3)) * 2, src, inb ? 16 : 0);
            }
        }
    };
    auto issueWs = [&](int t) {            // all KW taps of row di, chunk t/KH
        int chunk = t / KH, di = t - chunk * KH;   // cold path (once/stage)
        int c0 = chunk << 5;
        uint32_t wdst = blob + WS_OFF + (t & 1) * WS_SLOTB;
        int total = KW << 9;               // KW*128*4
        for (int idx = tid; idx < total; idx += 256) {
            int dj  = idx >> 9;
            int rem = idx & 511;
            int mm = rem >> 2, seg = rem & 3;
            const __half* wsrc = g_wp + (((size_t)(di * 3 + dj) * 1024 + m0 + mm) << 9) + c0;
            CP16(wdst + dj * WS_TAPB + (mm * XS_STRIDE + (seg << 3)) * 2,
                 wsrc + (seg << 3), 16);
        }
    };

    issueXs(0); issueWs(0);
    asm volatile("cp.async.commit_group;");

    int chunk = 0, di = 0;
    for (int t = 0; t < T; t++) {
        asm volatile("cp.async.wait_group 0;");
        __syncthreads();
        if (di == 0 && chunk + 1 < 16) issueXs(chunk + 1);
        if (t + 1 < T) issueWs(t + 1);
        asm volatile("cp.async.commit_group;");

        const uint32_t xb = blob + (chunk & 1) * XS_BUFB;
        const uint32_t wbase = blob + WS_OFF + (t & 1) * WS_SLOTB;
        const int prow = r + di;

        for (int dj = 0; dj < KW; dj++) {
            const uint32_t wb = wbase + dj * WS_TAPB;
            #pragma unroll
            for (int ks = 0; ks < 32; ks += 16) {
                uint32_t a[2][4], b[4][4];
                #pragma unroll
                for (int mt = 0; mt < 2; mt++) {
                    uint32_t addr = xb +
                        (((prow * 36 + mt * 16 + la15 + dj) * XS_STRIDE) + ks + lahi) * 2;
                    asm volatile("ldmatrix.sync.aligned.m8n8.x4.shared.b16 {%0,%1,%2,%3}, [%4];"
                                 : "=r"(a[mt][0]), "=r"(a[mt][1]), "=r"(a[mt][2]), "=r"(a[mt][3])
                                 : "r"(addr));
                }
                #pragma unroll
                for (int g = 0; g < 4; g++) {
                    uint32_t addr = wb + (((nbase + g * 16 + bm) * XS_STRIDE) + ks + bk) * 2;
                    asm volatile("ldmatrix.sync.aligned.m8n8.x4.shared.b16 {%0,%1,%2,%3}, [%4];"
                                 : "=r"(b[g][0]), "=r"(b[g][1]), "=r"(b[g][2]), "=r"(b[g][3])
                                 : "r"(addr));
                }
                #pragma unroll
                for (int mt = 0; mt < 2; mt++)
                    #pragma unroll
                    for (int nt = 0; nt < 8; nt++) {
                        asm volatile(
                            "mma.sync.aligned.m16n8k16.row.col.f32.f16.f16.f32 "
                            "{%0,%1,%2,%3}, {%4,%5,%6,%7}, {%8,%9}, {%0,%1,%2,%3};"
                            : "+f"(acc[mt][nt][0]), "+f"(acc[mt][nt][1]),
                              "+f"(acc[mt][nt][2]), "+f"(acc[mt][nt][3])
                            : "r"(a[mt][0]), "r"(a[mt][1]), "r"(a[mt][2]), "r"(a[mt][3]),
                              "r"(b[nt >> 1][(nt & 1) * 2]), "r"(b[nt >> 1][(nt & 1) * 2 + 1]));
                    }
            }
        }
        if (++di == KH) { di = 0; ++chunk; }
    }

    __syncthreads();   // smem -> BN partial staging reuse

    // ---- epilogue: bias, y(fp16), deterministic BN partials ----
    float* s_ps = reinterpret_cast<float*>(dsmem);         // [4][128]
    float* s_qs = reinterpret_cast<float*>(dsmem) + 512;   // [4][128]
    const int pbase = (n << 10) + ((i0 + r) << 5);
    const int pc = pbase + (lane >> 2);
    #pragma unroll
    for (int nt = 0; nt < 8; nt++) {
        int cl = nbase + nt * 8 + ((lane & 3) << 1);
        int mg = m0 + cl;
        float b0 = g_bias[mg], b1 = g_bias[mg + 1];
        float s0 = 0.f, q0 = 0.f, s1 = 0.f, q1 = 0.f;
        __half* y0 = g_y + (size_t)mg * 16384;
        __half* y1 = y0 + 16384;
        #pragma unroll
        for (int mt = 0; mt < 2; mt++) {
            int p = pc + mt * 16;
            float v00 = acc[mt][nt][0] + b0;
            float v01 = acc[mt][nt][1] + b1;
            float v10 = acc[mt][nt][2] + b0;
            float v11 = acc[mt][nt][3] + b1;
            y0[p]     = __float2half(v00);  y1[p]     = __float2half(v01);
            y0[p + 8] = __float2half(v10);  y1[p + 8] = __float2half(v11);
            s0 += v00 + v10;  q0 += v00 * v00 + v10 * v10;
            s1 += v01 + v11;  q1 += v01 * v01 + v11 * v11;
        }
        #pragma unroll
        for (int off = 4; off <= 16; off <<= 1) {
            s0 += __shfl_xor_sync(0xffffffffu, s0, off);
            q0 += __shfl_xor_sync(0xffffffffu, q0, off);
            s1 += __shfl_xor_sync(0xffffffffu, s1, off);
            q1 += __shfl_xor_sync(0xffffffffu, q1, off);
        }
        if (lane < 4) {
            s_ps[r * 128 + cl]     = s0;  s_qs[r * 128 + cl]     = q0;
            s_ps[r * 128 + cl + 1] = s1;  s_qs[r * 128 + cl + 1] = q1;
        }
    }
    __syncthreads();
    if (tid < 128) {
        float s = s_ps[tid] + s_ps[128 + tid] + s_ps[256 + tid] + s_ps[384 + tid];
        float q = s_qs[tid] + s_qs[128 + tid] + s_qs[256 + tid] + s_qs[384 + tid];
        g_psum[(size_t)(m0 + tid) * 128 + pb] = s;
        g_qsum[(size_t)(m0 + tid) * 128 + pb] = q;
    }
}

// ---------------- BN stats ------------------------------------------------------
__global__ void stats_kernel(const float* __restrict__ gamma, const float* __restrict__ beta) {
    __shared__ float sh_s[128], sh_q[128];
    int co = blockIdx.x;
    int t  = threadIdx.x;
    float s = 0.f, q = 0.f;
    #pragma unroll
    for (int conv = 0; conv < 4; conv++) {
        size_t base = (size_t)(conv * 256 + co) * 128 + t;
        s += g_psum[base];
        q += g_qsum[base];
    }
    sh_s[t] = s; sh_q[t] = q;
    __syncthreads();
    for (int off = 64; off >= 32; off >>= 1) {
        if (t < off) { sh_s[t] += sh_s[t + off]; sh_q[t] += sh_q[t + off]; }
        __syncthreads();
    }
    if (t < 32) {
        s = sh_s[t]; q = sh_q[t];
        #pragma unroll
        for (int off = 16; off >= 1; off >>= 1) {
            s += __shfl_xor_sync(0xffffffffu, s, off);
            q += __shfl_xor_sync(0xffffffffu, q, off);
        }
        if (t == 0) {
            float mean = s * (1.f / 65536.f);
            float var  = q * (1.f / 65536.f) - mean * mean;
            float sc   = gamma[co] * rsqrtf(var + 1e-5f);
            g_scale[co] = sc;
            g_shift[co] = beta[co] - mean * sc;
        }
    }
}

// ------------- BN apply + ReLU + pixel-shuffle interleave -----------------------
__global__ void bn_kernel(float* __restrict__ out) {
    int o4 = blockIdx.x * 256 + threadIdx.x;
    int o  = o4 << 2;
    int J  = o & 63;
    int I  = (o >> 6) & 63;
    int co = (o >> 12) & 255;
    int n  = o >> 20;
    int convA = (I & 1);
    int convB = (I & 1) | 2;
    int p = (n << 10) + ((I >> 1) << 5) + (J >> 1);
    const __half* ya = g_y + (size_t)((convA << 8) | co) * 16384 + p;
    const __half* yb = g_y + (size_t)((convB << 8) | co) * 16384 + p;
    __half2 a2 = *reinterpret_cast<const __half2*>(ya);
    __half2 b2 = *reinterpret_cast<const __half2*>(yb);
    float sa = g_scale[co], sha = g_shift[co];
    float4 r;
    r.x = fmaxf(__half2float(a2.x) * sa + sha, 0.f);
    r.y = fmaxf(__half2float(b2.x) * sa + sha, 0.f);
    r.z = fmaxf(__half2float(a2.y) * sa + sha, 0.f);
    r.w = fmaxf(__half2float(b2.y) * sa + sha, 0.f);
    reinterpret_cast<float4*>(out)[o4] = r;
}

// --------------------------------- launch ---------------------------------------
extern "C" void kernel_launch(void* const* d_in, const int* in_sizes, int n_in,
                              void* d_out, int out_size) {
    const float* x     = (const float*)d_in[0];
    const float* w1    = (const float*)d_in[1];
    const float* b1    = (const float*)d_in[2];
    const float* w2    = (const float*)d_in[3];
    const float* b2    = (const float*)d_in[4];
    const float* w3    = (const float*)d_in[5];
    const float* b3    = (const float*)d_in[6];
    const float* w4    = (const float*)d_in[7];
    const float* b4    = (const float*)d_in[8];
    const float* gamma = (const float*)d_in[9];
    const float* beta  = (const float*)d_in[10];
    float* out = (float*)d_out;

    static bool attr_set = false;
    if (!attr_set) {
        cudaFuncSetAttribute(conv_kernel, cudaFuncAttributeMaxDynamicSharedMemorySize, SMEM_BYTES);
        attr_set = true;
    }

    pack_weights_kernel<<<(9 * 1024 * 512 + 255) / 256, 256>>>(w1, w2, w3, w4);
    pack_misc_kernel<<<4, 256>>>(b1, b2, b3, b4);
    {
        dim3 g(512, 16);
        convert_x_kernel<<<g, 256>>>(x);
    }
    {
        dim3 grid(128, 8);
        conv_kernel<<<grid, 256, SMEM_BYTES>>>();
    }
    stats_kernel<<<256, 128>>>(gamma, beta);
    bn_kernel<<<(16777216 / 4) / 256, 256>>>(out);
}